// round 14
// baseline (speedup 1.0000x reference)
#include <cuda_runtime.h>

#define L_SEQ 1024
#define M_DIM 128
#define SPLIT 640              // role-A: steps [0,640); role-B: init [0,640) + full [640,1024)

// Final table, step-major, padded two steps (prefetch depth 2):
//   per step i: floats [0..127]   W[m] = dlt[m,i] * P0[m,i]   (P0 = prod_{j<i} e0[m,j])
//               floats [128..255] q[m] = dlt[m,i] / e0[m,i]
__device__ float g_tbl[(L_SEQ + 2) * 256];
__device__ float g_e0[L_SEQ * M_DIM];
__device__ float g_dl[L_SEQ * M_DIM];
__device__ float g_cp[8 * M_DIM];
__device__ float g_res[2][16384];       // per-role partial row sums

typedef unsigned long long u64;

__device__ __forceinline__ u64 pk2(float lo, float hi) {
    u64 r; asm("mov.b64 %0,{%1,%2};" : "=l"(r) : "f"(lo), "f"(hi)); return r;
}
__device__ __forceinline__ void upk2(u64 v, float& lo, float& hi) {
    asm("mov.b64 {%0,%1},%2;" : "=f"(lo), "=f"(hi) : "l"(v));
}
__device__ __forceinline__ u64 fma2(u64 a, u64 b, u64 c) {
    u64 r; asm("fma.rn.f32x2 %0,%1,%2,%3;" : "=l"(r) : "l"(a), "l"(b), "l"(c)); return r;
}
__device__ __forceinline__ u64 mul2(u64 a, u64 b) {
    u64 r; asm("mul.rn.f32x2 %0,%1,%2;" : "=l"(r) : "l"(a), "l"(b)); return r;
}
__device__ __forceinline__ u64 add2(u64 a, u64 b) {
    u64 r; asm("add.rn.f32x2 %0,%1,%2;" : "=l"(r) : "l"(a), "l"(b)); return r;
}
// predicated: if (s) { h0 = q0*h0 + h0; h1 = q1*h1 + h1; }
__device__ __forceinline__ void upd2(u64& h0, u64& h1, u64 q0, u64 q1, int s) {
    asm("{.reg .pred P; setp.ne.s32 P,%4,0;"
        "@P fma.rn.f32x2 %0,%2,%0,%0;"
        "@P fma.rn.f32x2 %1,%3,%1,%1;}"
        : "+l"(h0), "+l"(h1) : "l"(q0), "l"(q1), "r"(s));
}

// prepA: transpose eps [D,M,L] -> step-major e0 / dlt
__global__ void prepA(const float* __restrict__ eps) {
    int idx = blockIdx.x * blockDim.x + threadIdx.x;
    if (idx >= L_SEQ * M_DIM) return;
    int i = idx >> 7, m = idx & 127;
    float a = eps[(size_t)m * L_SEQ + i];
    float b = eps[(size_t)(M_DIM + m) * L_SEQ + i];
    g_e0[i * 128 + m] = a;
    g_dl[i * 128 + m] = b - a;
}

// prepB: per (m, chunk c of 128 steps) product of e0
__global__ void prepB() {
    int idx = blockIdx.x * blockDim.x + threadIdx.x;   // 0..1023
    int m = idx & 127, c = idx >> 7;
    float p = 1.f;
    #pragma unroll 8
    for (int t = 0; t < 128; t++)
        p *= g_e0[(c * 128 + t) * 128 + m];
    g_cp[c * 128 + m] = p;
}

// prepC: scan within chunk, write W and q; zero the 2 pad steps
__global__ void prepC() {
    int idx = blockIdx.x * blockDim.x + threadIdx.x;   // 0..1023
    int m = idx & 127, c = idx >> 7;
    float P = 1.f;
    for (int cc = 0; cc < c; cc++) P *= g_cp[cc * 128 + m];
    for (int t = 0; t < 128; t++) {
        int i = c * 128 + t;
        float e = g_e0[i * 128 + m];
        float d = g_dl[i * 128 + m];
        g_tbl[i * 256 + m]       = d * P;
        g_tbl[i * 256 + 128 + m] = __fdividef(d, e);
        P *= e;
    }
    if (c == 0) {
        g_tbl[L_SEQ * 256 + m] = 0.f;       g_tbl[L_SEQ * 256 + 128 + m] = 0.f;
        g_tbl[(L_SEQ + 1) * 256 + m] = 0.f; g_tbl[(L_SEQ + 1) * 256 + 128 + m] = 0.f;
    }
}

__global__ void combineK(float* __restrict__ out, int rows) {
    int r = blockIdx.x * blockDim.x + threadIdx.x;
    if (r < rows) out[r] = g_res[0][r] + g_res[1][r];
}

#define ST 33                  // u64 stride per step (32 entries + 1 pad)
#define A1OFF 280              // arr23 base: >= 8*33=264, and 280 % 16 == 8 (disjoint bank halves)
#define WBUF 560               // per-warp u64 buffer

__global__ __launch_bounds__(128, 6)
void arqgps_kernel(const int* __restrict__ inp, int nrows) {
    __shared__ alignas(16) u64 sp[4][WBUF];          // 4 warps x 4480 B = 17.9 KB
    const unsigned FULL = 0xffffffffu;
    const int lane = threadIdx.x & 31;
    const int wid  = threadIdx.x >> 5;

    const int halfGrid = (int)(gridDim.x >> 1);
    const bool roleB = ((int)blockIdx.x >= halfGrid);
    const int bx = roleB ? ((int)blockIdx.x - halfGrid) : (int)blockIdx.x;

    const int nrg = nrows >> 2;                      // 4 rows per warp
    const int rg_raw = bx * 4 + wid;
    const bool live = (rg_raw < nrg);
    const int rg = live ? rg_raw : (nrg - 1);        // clamp; never early-exit (ballots!)

    const ulonglong2* __restrict__ tb = reinterpret_cast<const ulonglong2*>(g_tbl);
    const int* __restrict__ p0r = inp + (size_t)(4 * rg) * L_SEQ;
    const int* __restrict__ p1r = p0r + L_SEQ;
    const int* __restrict__ p2r = p1r + L_SEQ;
    const int* __restrict__ p3r = p2r + L_SEQ;

    const u64 one2 = pk2(1.f, 1.f);
    u64 HA0 = one2, HA1 = one2, HB0 = one2, HB1 = one2;   // rows 0,1 (4 m/lane each)
    u64 HC0 = one2, HC1 = one2, HD0 = one2, HD1 = one2;   // rows 2,3

    // lse identity: lane owns (row = lane>>3, step-in-window = lane&7), window = 8 steps
    const int myrow = lane >> 3;
    const int kb    = lane & 7;

    u64* const wp0 = &sp[wid][lane];                      // pair(0,1), wp0[t*ST]
    u64* const wp1 = &sp[wid][A1OFF + lane];              // pair(2,3)
    const u64* const rbase = &sp[wid][((myrow & 2) ? A1OFF : 0) + kb * ST];

    float acc = 0.f;
    int   c1m = 0;                                        // 1-count for MY row before window

    // ===================== role B: init pass over [0, SPLIT) =====================
    if (roleB) {
        const ulonglong2* __restrict__ qp = tb + 32 + lane;    // Q of step i at qp[i*64]
        ulonglong2 Qc = qp[0], Qn = qp[64];
        unsigned b0 = __ballot_sync(FULL, __ldg(p0r + lane) & 1);
        unsigned b1 = __ballot_sync(FULL, __ldg(p1r + lane) & 1);
        unsigned b2 = __ballot_sync(FULL, __ldg(p2r + lane) & 1);
        unsigned b3 = __ballot_sync(FULL, __ldg(p3r + lane) & 1);

        for (int i0 = 0; i0 < SPLIT; i0 += 32) {
            const int nx = i0 + 32;
            const bool more = (nx < SPLIT);
            const unsigned n0 = __ballot_sync(FULL, (more ? __ldg(p0r + nx + lane) : 0) & 1);
            const unsigned n1 = __ballot_sync(FULL, (more ? __ldg(p1r + nx + lane) : 0) & 1);
            const unsigned n2 = __ballot_sync(FULL, (more ? __ldg(p2r + nx + lane) : 0) & 1);
            const unsigned n3 = __ballot_sync(FULL, (more ? __ldg(p3r + nx + lane) : 0) & 1);

            #pragma unroll
            for (int k = 0; k < 32; k++) {
                ulonglong2 Q2 = qp[(size_t)(i0 + k + 2) * 64];
                upd2(HA0, HA1, Qc.x, Qc.y, (int)((b0 >> k) & 1u));
                upd2(HB0, HB1, Qc.x, Qc.y, (int)((b1 >> k) & 1u));
                upd2(HC0, HC1, Qc.x, Qc.y, (int)((b2 >> k) & 1u));
                upd2(HD0, HD1, Qc.x, Qc.y, (int)((b3 >> k) & 1u));
                Qc = Qn; Qn = Q2;
            }
            const unsigned mybits = (myrow == 0) ? b0 : (myrow == 1) ? b1
                                  : (myrow == 2) ? b2 : b3;
            c1m += __popc(mybits);
            b0 = n0; b1 = n1; b2 = n2; b3 = n3;
        }
    }

    // ===================== full phase: [beg, end) =====================
    const int beg = roleB ? SPLIT : 0;
    const int end = roleB ? L_SEQ : SPLIT;

    ulonglong2 Wc = tb[(size_t)beg * 64 + lane];
    ulonglong2 Qc = tb[(size_t)beg * 64 + 32 + lane];
    ulonglong2 Wn = tb[(size_t)(beg + 1) * 64 + lane];
    ulonglong2 Qn = tb[(size_t)(beg + 1) * 64 + 32 + lane];

    unsigned b0 = __ballot_sync(FULL, __ldg(p0r + beg + lane) & 1);
    unsigned b1 = __ballot_sync(FULL, __ldg(p1r + beg + lane) & 1);
    unsigned b2 = __ballot_sync(FULL, __ldg(p2r + beg + lane) & 1);
    unsigned b3 = __ballot_sync(FULL, __ldg(p3r + beg + lane) & 1);

    for (int i0 = beg; i0 < end; i0 += 32) {
        const int nx = i0 + 32;
        const bool more = (nx < end);
        const unsigned n0 = __ballot_sync(FULL, (more ? __ldg(p0r + nx + lane) : 0) & 1);
        const unsigned n1 = __ballot_sync(FULL, (more ? __ldg(p1r + nx + lane) : 0) & 1);
        const unsigned n2 = __ballot_sync(FULL, (more ? __ldg(p2r + nx + lane) : 0) & 1);
        const unsigned n3 = __ballot_sync(FULL, (more ? __ldg(p3r + nx + lane) : 0) & 1);
        const unsigned mybits = (myrow == 0) ? b0 : (myrow == 1) ? b1
                              : (myrow == 2) ? b2 : b3;

        #pragma unroll
        for (int w = 0; w < 4; w++) {
            // ---- write phase: 8 steps ----
            #pragma unroll
            for (int t = 0; t < 8; t++) {
                const int k = w * 8 + t;
                ulonglong2 W2 = tb[(size_t)(i0 + k + 2) * 64 + lane];
                ulonglong2 Q2 = tb[(size_t)(i0 + k + 2) * 64 + 32 + lane];

                u64 pA = fma2(Wc.y, HA1, mul2(Wc.x, HA0));
                u64 pB = fma2(Wc.y, HB1, mul2(Wc.x, HB0));
                u64 pC = fma2(Wc.y, HC1, mul2(Wc.x, HC0));
                u64 pD = fma2(Wc.y, HD1, mul2(Wc.x, HD0));

                upd2(HA0, HA1, Qc.x, Qc.y, (int)((b0 >> k) & 1u));
                upd2(HB0, HB1, Qc.x, Qc.y, (int)((b1 >> k) & 1u));
                upd2(HC0, HC1, Qc.x, Qc.y, (int)((b2 >> k) & 1u));
                upd2(HD0, HD1, Qc.x, Qc.y, (int)((b3 >> k) & 1u));

                float fa0, fa1, fb0, fb1, fc0, fc1, fd0, fd1;
                upk2(pA, fa0, fa1); upk2(pB, fb0, fb1);
                upk2(pC, fc0, fc1); upk2(pD, fd0, fd1);
                wp0[t * ST] = pk2(fa0 + fa1, fb0 + fb1);   // (row0, row1)
                wp1[t * ST] = pk2(fc0 + fc1, fd0 + fd1);   // (row2, row3)

                Wc = Wn; Qc = Qn; Wn = W2; Qn = Q2;
            }
            __syncwarp();

            // ---- read phase: lane sums 32 entries of its (pair, step) ----
            u64 s0 = rbase[0], s1 = rbase[1], s2 = rbase[2], s3 = rbase[3];
            #pragma unroll
            for (int l = 4; l < 32; l += 4) {
                s0 = add2(s0, rbase[l]);
                s1 = add2(s1, rbase[l + 1]);
                s2 = add2(s2, rbase[l + 2]);
                s3 = add2(s3, rbase[l + 3]);
            }
            u64 st = add2(add2(s0, s1), add2(s2, s3));
            float dr0, dr1; upk2(st, dr0, dr1);
            const float dxt = (myrow & 1) ? dr1 : dr0;

            // lse for (row = myrow, step = i0 + w*8 + kb)
            const int kk  = w * 8 + kb;
            const int s   = (int)((mybits >> kk) & 1u);
            const int c1i = c1m + __popc(mybits & ((1u << kk) - 1u));
            const int i   = i0 + kk;

            const float sgn = s ? dxt : -dxt;
            const float contrib = fminf(0.f, sgn)
                                - 0.5f * __logf(1.f + __expf(-2.f * fabsf(dxt)));
            const bool dead_other = s ? ((i - c1i) >= 512) : (c1i >= 512);
            acc += dead_other ? 0.f : contrib;

            __syncwarp();                    // next window's writers wait for readers
        }

        c1m += __popc(mybits);
        b0 = n0; b1 = n1; b2 = n2; b3 = n3;
    }

    // sum acc across the 8 lanes owning each row (xor < 8 stays in row group)
    acc += __shfl_xor_sync(FULL, acc, 1);
    acc += __shfl_xor_sync(FULL, acc, 2);
    acc += __shfl_xor_sync(FULL, acc, 4);

    if (live && kb == 0) g_res[roleB ? 1 : 0][4 * rg + myrow] = acc;
}

extern "C" void kernel_launch(void* const* d_in, const int* in_sizes, int n_in,
                              void* d_out, int out_size) {
    const int*   inp = nullptr;
    const float* eps = nullptr;
    int rows = 0;
    if (in_sizes[0] == 2 * M_DIM * L_SEQ) {
        eps = (const float*)d_in[0];
        inp = (const int*)d_in[1];
        rows = in_sizes[1] / L_SEQ;
    } else {
        inp = (const int*)d_in[0];
        eps = (const float*)d_in[1];
        rows = in_sizes[0] / L_SEQ;
    }

    { int n = L_SEQ * M_DIM; prepA<<<(n + 255) / 256, 256>>>(eps); }
    prepB<<<4, 256>>>();
    prepC<<<4, 256>>>();
    {
        // 4 warps/block, 4 rows/warp, doubled grid (role A + role B)
        int nrg = rows / 4;
        int blocksPerRole = (nrg + 3) / 4;
        arqgps_kernel<<<2 * blocksPerRole, 128>>>(inp, rows);
    }
    combineK<<<(rows + 255) / 256, 256>>>((float*)d_out, rows);
}

// round 15
// speedup vs baseline: 1.3698x; 1.3698x over previous
#include <cuda_runtime.h>
#include <cuda_bf16.h>

#define L_SEQ 1024
#define M_DIM 128

// Final table, step-major, 768 B per step, padded two steps (prefetch depth 2):
//   per step i: bytes [0..255]   W[m] as bf16 (128 values) = dlt[m,i] * P0[m,i]
//               bytes [256..767] q[m] as fp32 (128 values) = dlt[m,i] / e0[m,i]
// (P0 = prod_{j<i} e0[m,j])
__device__ float g_tbl[(L_SEQ + 2) * 192];
__device__ float g_e0[L_SEQ * M_DIM];
__device__ float g_dl[L_SEQ * M_DIM];
__device__ float g_cp[8 * M_DIM];

typedef unsigned long long u64;
typedef unsigned int u32;

__device__ __forceinline__ u64 pk2(float lo, float hi) {
    u64 r; asm("mov.b64 %0,{%1,%2};" : "=l"(r) : "f"(lo), "f"(hi)); return r;
}
__device__ __forceinline__ u64 pk2u(u32 lo, u32 hi) {
    u64 r; asm("mov.b64 %0,{%1,%2};" : "=l"(r) : "r"(lo), "r"(hi)); return r;
}
__device__ __forceinline__ void upk2(u64 v, float& lo, float& hi) {
    asm("mov.b64 {%0,%1},%2;" : "=f"(lo), "=f"(hi) : "l"(v));
}
__device__ __forceinline__ u64 fma2(u64 a, u64 b, u64 c) {
    u64 r; asm("fma.rn.f32x2 %0,%1,%2,%3;" : "=l"(r) : "l"(a), "l"(b), "l"(c)); return r;
}
__device__ __forceinline__ u64 mul2(u64 a, u64 b) {
    u64 r; asm("mul.rn.f32x2 %0,%1,%2;" : "=l"(r) : "l"(a), "l"(b)); return r;
}
__device__ __forceinline__ u64 add2(u64 a, u64 b) {
    u64 r; asm("add.rn.f32x2 %0,%1,%2;" : "=l"(r) : "l"(a), "l"(b)); return r;
}
// predicated: if (sm != 0) { h0 = q0*h0 + h0; h1 = q1*h1 + h1; }
__device__ __forceinline__ void upd2(u64& h0, u64& h1, u64 q0, u64 q1, u32 sm) {
    asm("{.reg .pred P; setp.ne.u32 P,%4,0;"
        "@P fma.rn.f32x2 %0,%2,%0,%0;"
        "@P fma.rn.f32x2 %1,%3,%1,%1;}"
        : "+l"(h0), "+l"(h1) : "l"(q0), "l"(q1), "r"(sm));
}
__device__ __forceinline__ u64 shfl64_xor(unsigned mask, u64 v, int o) {
    double d = __longlong_as_double((long long)v);
    d = __shfl_xor_sync(mask, d, o);
    return (u64)__double_as_longlong(d);
}

// prepA: transpose eps [D,M,L] -> step-major e0 / dlt
__global__ void prepA(const float* __restrict__ eps) {
    int idx = blockIdx.x * blockDim.x + threadIdx.x;
    if (idx >= L_SEQ * M_DIM) return;
    int i = idx >> 7, m = idx & 127;
    float a = eps[(size_t)m * L_SEQ + i];
    float b = eps[(size_t)(M_DIM + m) * L_SEQ + i];
    g_e0[i * 128 + m] = a;
    g_dl[i * 128 + m] = b - a;
}

// prepB: per (m, chunk c of 128 steps) product of e0
__global__ void prepB() {
    int idx = blockIdx.x * blockDim.x + threadIdx.x;   // 0..1023
    int m = idx & 127, c = idx >> 7;
    float p = 1.f;
    #pragma unroll 8
    for (int t = 0; t < 128; t++)
        p *= g_e0[(c * 128 + t) * 128 + m];
    g_cp[c * 128 + m] = p;
}

// prepC: scan within chunk, write W (bf16) and q (fp32); zero the 2 pad steps
__global__ void prepC() {
    int idx = blockIdx.x * blockDim.x + threadIdx.x;   // 0..1023
    int m = idx & 127, c = idx >> 7;
    float P = 1.f;
    for (int cc = 0; cc < c; cc++) P *= g_cp[cc * 128 + m];
    char* base = reinterpret_cast<char*>(g_tbl);
    for (int t = 0; t < 128; t++) {
        int i = c * 128 + t;
        float e = g_e0[i * 128 + m];
        float d = g_dl[i * 128 + m];
        *reinterpret_cast<__nv_bfloat16*>(base + (size_t)i * 768 + m * 2) =
            __float2bfloat16(d * P);
        *reinterpret_cast<float*>(base + (size_t)i * 768 + 256 + m * 4) =
            __fdividef(d, e);
        P *= e;
    }
    if (c == 0) {
        for (int pi = L_SEQ; pi < L_SEQ + 2; pi++) {
            *reinterpret_cast<__nv_bfloat16*>(base + (size_t)pi * 768 + m * 2) =
                __float2bfloat16(0.f);
            *reinterpret_cast<float*>(base + (size_t)pi * 768 + 256 + m * 4) = 0.f;
        }
    }
}

#define WIN 16                 // reduction window (steps)
#define ST 34                  // u64 stride per step (even -> 16B alignment for LDS.128)
#define WROW 546               // per-warp u64 count (16*34 + 2 pad)

__global__ __launch_bounds__(128, 7)
void arqgps_kernel(const int* __restrict__ inp, float* __restrict__ out, int nrows) {
    __shared__ alignas(16) u64 sp[4][WROW];      // 4 warps x 4368 B = 17.5 KB
    const unsigned FULL = 0xffffffffu;
    const int lane = threadIdx.x & 31;
    const int wid  = threadIdx.x >> 5;
    const int nrg  = nrows >> 1;                 // one row-pair per warp
    const int rg_raw = blockIdx.x * 4 + wid;
    const bool live = (rg_raw < nrg);
    const int rg = live ? rg_raw : (nrg - 1);    // clamp; never early-exit (ballots!)

    const char* __restrict__ tbase = reinterpret_cast<const char*>(g_tbl);
    const int* __restrict__ i0p = inp + (size_t)(2 * rg) * L_SEQ;
    const int* __restrict__ i1p = i0p + L_SEQ;

    const u64 one2 = pk2(1.f, 1.f);
    u64 H0[2] = {one2, one2}, H1[2] = {one2, one2};   // 4 m per row

    // this lane finalizes (row = wrow, window-step = wstep); reads half the entries
    const int wstep = lane & 15;
    const int wrow  = lane >> 4;

    u64* const wp = &sp[wid][lane];              // writer base: wp[t*ST]
    const ulonglong2* const rb =
        reinterpret_cast<const ulonglong2*>(&sp[wid][wstep * ST + 16 * wrow]);

    float acc = 0.f;
    int   c1m = 0;                               // 1-count for MY row before window

    // depth-2 tile pipeline: Wraw = 4 bf16 (u64 load), Q = 2 fp32x2 (ulonglong2)
    u64 Wrc = *reinterpret_cast<const u64*>(tbase + (size_t)lane * 8);
    ulonglong2 Qc = *reinterpret_cast<const ulonglong2*>(tbase + 256 + (size_t)lane * 16);
    u64 Wrn = *reinterpret_cast<const u64*>(tbase + 768 + (size_t)lane * 8);
    ulonglong2 Qn = *reinterpret_cast<const ulonglong2*>(tbase + 768 + 256 + (size_t)lane * 16);

    unsigned bits0 = __ballot_sync(FULL, __ldg(i0p + lane) & 1);   // s for 32 steps, row0
    unsigned bits1 = __ballot_sync(FULL, __ldg(i1p + lane) & 1);   // row1

    for (int i0 = 0; i0 < L_SEQ; i0 += 32) {
        const int nx = i0 + 32;
        const int iv0n = (nx < L_SEQ) ? __ldg(i0p + nx + lane) : 0;
        const int iv1n = (nx < L_SEQ) ? __ldg(i1p + nx + lane) : 0;
        const unsigned bn0 = __ballot_sync(FULL, iv0n & 1);
        const unsigned bn1 = __ballot_sync(FULL, iv1n & 1);
        const char* __restrict__ bb = tbase + (size_t)i0 * 768;

        #pragma unroll
        for (int h = 0; h < 2; h++) {
            // ---- write phase: 16 steps ----
            #pragma unroll
            for (int t = 0; t < WIN; t++) {
                const int k = h * WIN + t;
                // prefetch step k+2 (immediate offsets off bb; pad-safe)
                u64 W2 = *reinterpret_cast<const u64*>(bb + (size_t)(k + 2) * 768 + lane * 8);
                ulonglong2 Q2 = *reinterpret_cast<const ulonglong2*>(
                                    bb + (size_t)(k + 2) * 768 + 256 + lane * 16);

                // expand 4 bf16 W -> 2 fp32x2 (4 PRMT)
                const u32 wlo = (u32)Wrc, whi = (u32)(Wrc >> 32);
                u64 Wx = pk2u(__byte_perm(wlo, 0, 0x1044), __byte_perm(wlo, 0, 0x3244));
                u64 Wy = pk2u(__byte_perm(whi, 0, 0x1044), __byte_perm(whi, 0, 0x3244));

                u64 p0 = fma2(Wy, H0[1], mul2(Wx, H0[0]));   // row0, 4 m packed
                u64 p1 = fma2(Wy, H1[1], mul2(Wx, H1[0]));   // row1

                upd2(H0[0], H0[1], Qc.x, Qc.y, bits0 & (1u << k));
                upd2(H1[0], H1[1], Qc.x, Qc.y, bits1 & (1u << k));

                float a0, a1, a2, a3;
                upk2(p0, a0, a1); upk2(p1, a2, a3);
                wp[t * ST] = pk2(a0 + a1, a2 + a3);          // (row0, row1) partial

                Wrc = Wrn; Qc = Qn; Wrn = W2; Qn = Q2;
            }
            __syncwarp();

            // ---- read phase: lane sums its HALF (16 entries) of step (lane&15),
            //      one 64-bit xor-16 shuffle completes the 32-entry sum ----
            ulonglong2 L0 = rb[0], L1 = rb[1], L2 = rb[2], L3 = rb[3];
            ulonglong2 L4 = rb[4], L5 = rb[5], L6 = rb[6], L7 = rb[7];
            u64 s0 = add2(L0.x, L0.y), s1 = add2(L1.x, L1.y);
            u64 s2 = add2(L2.x, L2.y), s3 = add2(L3.x, L3.y);
            s0 = add2(s0, add2(L4.x, L4.y));
            s1 = add2(s1, add2(L5.x, L5.y));
            s2 = add2(s2, add2(L6.x, L6.y));
            s3 = add2(s3, add2(L7.x, L7.y));
            u64 half_ = add2(add2(s0, s1), add2(s2, s3));
            u64 st = add2(half_, shfl64_xor(FULL, half_, 16));
            float dr0, dr1; upk2(st, dr0, dr1);
            const float dxt = wrow ? dr1 : dr0;

            // lse for (row = wrow, step = i0 + h*16 + wstep)
            const unsigned bw = ((wrow ? bits1 : bits0) >> (h * WIN)) & 0xffffu;
            const int s   = (int)((bw >> wstep) & 1u);
            const int c1i = c1m + __popc(bw & ((1u << wstep) - 1u));
            const int i   = i0 + h * WIN + wstep;

            const float sgn = s ? dxt : -dxt;
            const float contrib = fminf(0.f, sgn)
                                - 0.5f * __logf(1.f + __expf(-2.f * fabsf(dxt)));
            const bool dead_other = s ? ((i - c1i) >= 512) : (c1i >= 512);
            acc += dead_other ? 0.f : contrib;

            c1m += __popc(bw);
            __syncwarp();                        // writers of next window wait for readers
        }

        bits0 = bn0; bits1 = bn1;
    }

    // sum acc across the 16 lanes owning each row (xor < 16 stays in-group)
    acc += __shfl_xor_sync(FULL, acc, 1);
    acc += __shfl_xor_sync(FULL, acc, 2);
    acc += __shfl_xor_sync(FULL, acc, 4);
    acc += __shfl_xor_sync(FULL, acc, 8);

    if (live && (lane & 15) == 0) out[2 * rg + wrow] = acc;
}

extern "C" void kernel_launch(void* const* d_in, const int* in_sizes, int n_in,
                              void* d_out, int out_size) {
    const int*   inp = nullptr;
    const float* eps = nullptr;
    int rows = 0;
    if (in_sizes[0] == 2 * M_DIM * L_SEQ) {
        eps = (const float*)d_in[0];
        inp = (const int*)d_in[1];
        rows = in_sizes[1] / L_SEQ;
    } else {
        inp = (const int*)d_in[0];
        eps = (const float*)d_in[1];
        rows = in_sizes[0] / L_SEQ;
    }

    { int n = L_SEQ * M_DIM; prepA<<<(n + 255) / 256, 256>>>(eps); }
    prepB<<<4, 256>>>();
    prepC<<<4, 256>>>();
    {
        // one warp per row-pair; 4 warps (8 rows) per 128-thread block
        int nrg = rows / 2;
        int grid = (nrg + 3) / 4;
        arqgps_kernel<<<grid, 128>>>(inp, (float*)d_out, rows);
    }
}